// round 4
// baseline (speedup 1.0000x reference)
#include <cuda_runtime.h>

#define NN 100000
#define NE 1600000
#define SCAN_BLK ((NN + 1023) / 1024)   // 98

// ---------------- scratch (static device allocations only) ----------------
__device__ float g_T[NN * 128];
__device__ float g_H1[NN * 128];
__device__ float g_H2[NN * 128];
__device__ float g_norm_out[NN];
__device__ float g_norm_in[NN];
__device__ int   g_deg_out[NN];
__device__ int   g_deg_in[NN];
__device__ int   g_rowptr[NN + 1];
__device__ int   g_fill[NN];
__device__ int   g_col[NE];
__device__ int   g_bsum[SCAN_BLK];
__device__ int   g_is64;

// ---------------- index dtype detection ----------------
__global__ void detect_kernel(const int* __restrict__ src_raw) {
    if (threadIdx.x == 0 && blockIdx.x == 0) {
        int is64 = 1;
        for (int i = 0; i < 64; ++i)
            if (src_raw[2 * i + 1] != 0) { is64 = 0; break; }
        g_is64 = is64;
    }
}

__device__ __forceinline__ int load_idx(const void* p, int e, int is64) {
    if (is64) return (int)((const long long*)p)[e];
    return ((const int*)p)[e];
}

// ---------------- graph preprocessing ----------------
__global__ void init_kernel() {
    int i = blockIdx.x * blockDim.x + threadIdx.x;
    if (i < NN) { g_deg_out[i] = 0; g_deg_in[i] = 0; g_fill[i] = 0; }
}

__global__ void count_kernel(const void* __restrict__ src,
                             const void* __restrict__ dst) {
    int e = blockIdx.x * blockDim.x + threadIdx.x;
    int is64 = g_is64;
    if (e < NE) {
        atomicAdd(&g_deg_out[load_idx(src, e, is64)], 1);
        atomicAdd(&g_deg_in[load_idx(dst, e, is64)], 1);
    }
}

__global__ __launch_bounds__(1024) void scanA_kernel() {
    __shared__ int wsum[32];
    int i = blockIdx.x * 1024 + threadIdx.x;
    int lane = threadIdx.x & 31, wid = threadIdx.x >> 5;
    int v = (i < NN) ? g_deg_in[i] : 0;
    int x = v;
    #pragma unroll
    for (int o = 1; o < 32; o <<= 1) {
        int t = __shfl_up_sync(0xffffffffu, x, o);
        if (lane >= o) x += t;
    }
    if (lane == 31) wsum[wid] = x;
    __syncthreads();
    if (wid == 0) {
        int y = wsum[lane];
        #pragma unroll
        for (int o = 1; o < 32; o <<= 1) {
            int t = __shfl_up_sync(0xffffffffu, y, o);
            if (lane >= o) y += t;
        }
        wsum[lane] = y;
    }
    __syncthreads();
    int excl = x - v + (wid > 0 ? wsum[wid - 1] : 0);
    if (i < NN) g_rowptr[i] = excl;
    if (threadIdx.x == 1023) g_bsum[blockIdx.x] = excl + v;
}

__global__ void scanB_kernel() {
    if (threadIdx.x == 0) {
        int s = 0;
        for (int b = 0; b < SCAN_BLK; ++b) {
            int t = g_bsum[b];
            g_bsum[b] = s;
            s += t;
        }
        g_rowptr[NN] = s;
    }
}

__global__ void scanC_norm_kernel() {
    int i = blockIdx.x * blockDim.x + threadIdx.x;
    if (i < NN) {
        g_rowptr[i] += g_bsum[i >> 10];
        g_norm_out[i] = rsqrtf((float)max(g_deg_out[i], 1));
        g_norm_in[i]  = rsqrtf((float)max(g_deg_in[i], 1));
    }
}

__global__ void fill_kernel(const void* __restrict__ src,
                            const void* __restrict__ dst) {
    int e = blockIdx.x * blockDim.x + threadIdx.x;
    int is64 = g_is64;
    if (e < NE) {
        int d = load_idx(dst, e, is64);
        int p = g_rowptr[d] + atomicAdd(&g_fill[d], 1);
        g_col[p] = load_idx(src, e, is64);
    }
}

// ---------------- tf32 helpers ----------------
__device__ __forceinline__ void tf32split(float x, unsigned& hi, unsigned& lo) {
    unsigned h;
    asm("cvt.rna.tf32.f32 %0, %1;" : "=r"(h) : "f"(x));
    float lf = x - __uint_as_float(h);
    unsigned l;
    asm("cvt.rna.tf32.f32 %0, %1;" : "=r"(l) : "f"(lf));
    hi = h; lo = l;
}

__device__ __forceinline__ void mma_tf32(float* c, const unsigned* a, const unsigned* b) {
    asm volatile(
        "mma.sync.aligned.m16n8k8.row.col.f32.tf32.tf32.f32 "
        "{%0,%1,%2,%3}, {%4,%5,%6,%7}, {%8,%9}, {%0,%1,%2,%3};\n"
        : "+f"(c[0]), "+f"(c[1]), "+f"(c[2]), "+f"(c[3])
        : "r"(a[0]), "r"(a[1]), "r"(a[2]), "r"(a[3]), "r"(b[0]), "r"(b[1]));
}

// ---------------- tensor-core GEMM: g_T = (A @ W) * norm_out[:,None] ----------------
// A [NN,128] row-major, W [128,BN] row-major.
// SRCSEL: 0 = Xext, 1 = g_H1, 2 = 0.9*g_H1 + 0.1*g_H2
// 3xTF32 compensated: full-precision-ish via hi/lo split.
template <int BN, int SRCSEL>
__global__ __launch_bounds__(256) void gemm_tc_kernel(const float* __restrict__ Xext,
                                                      const float* __restrict__ W) {
    constexpr int BK = 32;
    constexpr int WARPS_N = BN / 32;        // 4 (BN=128) or 2 (BN=64)
    constexpr int WM = 128 / (8 / WARPS_N); // 64 or 32
    constexpr int MFR = WM / 16;            // 4 or 2
    constexpr int NFR = 4;                  // 32/8
    constexpr int LDS_ = 136;               // padded row stride (conflict-free)

    __shared__ float As[BK][LDS_];   // [k][m], transposed A tile
    __shared__ float Ws[BK][LDS_];   // [k][n]

    const int tid = threadIdx.x;
    const int w = tid >> 5, lane = tid & 31;
    const int gid = lane >> 2, tig = lane & 3;
    const int warp_n = (w % WARPS_N) * 32;
    const int warp_m = (w / WARPS_N) * WM;
    const int m0 = blockIdx.x * 128;

    float acc[MFR][NFR][4];
    #pragma unroll
    for (int a = 0; a < MFR; ++a)
        #pragma unroll
        for (int b = 0; b < NFR; ++b)
            #pragma unroll
            for (int c = 0; c < 4; ++c) acc[a][b][c] = 0.f;

    for (int kc = 0; kc < 128; kc += BK) {
        // --- A tile: 128 rows x 32 cols, transpose into As[k][m] ---
        #pragma unroll
        for (int l = 0; l < 4; ++l) {
            int lin = tid + l * 256;
            int row = lin >> 3;              // 8 float4 per 32-col row
            int kq  = (lin & 7) << 2;
            int gr  = m0 + row;
            float4 v = make_float4(0.f, 0.f, 0.f, 0.f);
            if (gr < NN) {
                if (SRCSEL == 0) {
                    v = *(const float4*)(Xext + gr * 128 + kc + kq);
                } else if (SRCSEL == 1) {
                    v = *(const float4*)(g_H1 + gr * 128 + kc + kq);
                } else {
                    float4 a = *(const float4*)(g_H1 + gr * 128 + kc + kq);
                    float4 b = *(const float4*)(g_H2 + gr * 128 + kc + kq);
                    v = make_float4(0.9f * a.x + 0.1f * b.x,
                                    0.9f * a.y + 0.1f * b.y,
                                    0.9f * a.z + 0.1f * b.z,
                                    0.9f * a.w + 0.1f * b.w);
                }
            }
            As[kq + 0][row] = v.x;
            As[kq + 1][row] = v.y;
            As[kq + 2][row] = v.z;
            As[kq + 3][row] = v.w;
        }
        // --- W tile: 32 x BN ---
        #pragma unroll
        for (int l = 0; l < BN / 32; ++l) {
            int lin = tid + l * 256;
            int k  = lin / (BN / 4);
            int nq = (lin % (BN / 4)) * 4;
            *(float4*)&Ws[k][nq] = *(const float4*)(W + (kc + k) * BN + nq);
        }
        __syncthreads();

        #pragma unroll
        for (int ks = 0; ks < BK; ks += 8) {
            // B fragments (hi/lo)
            unsigned bh[NFR][2], bl[NFR][2];
            #pragma unroll
            for (int nf = 0; nf < NFR; ++nf) {
                float x0 = Ws[ks + tig][warp_n + nf * 8 + gid];
                float x1 = Ws[ks + tig + 4][warp_n + nf * 8 + gid];
                tf32split(x0, bh[nf][0], bl[nf][0]);
                tf32split(x1, bh[nf][1], bl[nf][1]);
            }
            #pragma unroll
            for (int mf = 0; mf < MFR; ++mf) {
                unsigned ah[4], al[4];
                float x0 = As[ks + tig][warp_m + mf * 16 + gid];       // a0: r=gid,   c=tig
                float x1 = As[ks + tig][warp_m + mf * 16 + 8 + gid];   // a1: r=gid+8, c=tig
                float x2 = As[ks + tig + 4][warp_m + mf * 16 + gid];   // a2: r=gid,   c=tig+4
                float x3 = As[ks + tig + 4][warp_m + mf * 16 + 8 + gid]; // a3
                tf32split(x0, ah[0], al[0]);
                tf32split(x1, ah[1], al[1]);
                tf32split(x2, ah[2], al[2]);
                tf32split(x3, ah[3], al[3]);
                #pragma unroll
                for (int nf = 0; nf < NFR; ++nf) {
                    mma_tf32(acc[mf][nf], ah, bh[nf]);
                    mma_tf32(acc[mf][nf], ah, bl[nf]);
                    mma_tf32(acc[mf][nf], al, bh[nf]);
                }
            }
        }
        __syncthreads();
    }

    // epilogue: scale by norm_out, store g_T
    #pragma unroll
    for (int mf = 0; mf < MFR; ++mf) {
        int r0 = m0 + warp_m + mf * 16 + gid;
        int r1 = r0 + 8;
        float no0 = (r0 < NN) ? g_norm_out[r0] : 0.f;
        float no1 = (r1 < NN) ? g_norm_out[r1] : 0.f;
        #pragma unroll
        for (int nf = 0; nf < NFR; ++nf) {
            int col = warp_n + nf * 8 + 2 * tig;
            if (r0 < NN) {
                float2 v = make_float2(acc[mf][nf][0] * no0, acc[mf][nf][1] * no0);
                *(float2*)&g_T[r0 * BN + col] = v;
            }
            if (r1 < NN) {
                float2 v = make_float2(acc[mf][nf][2] * no1, acc[mf][nf][3] * no1);
                *(float2*)&g_T[r1 * BN + col] = v;
            }
        }
    }
}

// ---------------- aggregation ----------------
template <int FEAT, bool RELU, int OUTSEL>   // OUTSEL: 0=g_H1, 1=g_H2, 2=Oext
__global__ __launch_bounds__(256) void agg_kernel(const float* __restrict__ bias,
                                                  float* __restrict__ Oext) {
    int w = (blockIdx.x * 256 + threadIdx.x) >> 5;
    int lane = threadIdx.x & 31;
    if (w >= NN) return;
    int s0 = g_rowptr[w];
    int s1 = g_rowptr[w + 1];
    float ni = g_norm_in[w];

    if (FEAT == 128) {
        const int off = lane * 4;
        float4 a = make_float4(0.f, 0.f, 0.f, 0.f);
        int e = s0;
        for (; e + 4 <= s1; e += 4) {
            int c0 = g_col[e + 0], c1 = g_col[e + 1];
            int c2 = g_col[e + 2], c3 = g_col[e + 3];
            float4 t0 = *(const float4*)(g_T + c0 * 128 + off);
            float4 t1 = *(const float4*)(g_T + c1 * 128 + off);
            float4 t2 = *(const float4*)(g_T + c2 * 128 + off);
            float4 t3 = *(const float4*)(g_T + c3 * 128 + off);
            a.x += t0.x + t1.x + t2.x + t3.x;
            a.y += t0.y + t1.y + t2.y + t3.y;
            a.z += t0.z + t1.z + t2.z + t3.z;
            a.w += t0.w + t1.w + t2.w + t3.w;
        }
        for (; e < s1; ++e) {
            int c = g_col[e];
            float4 t = *(const float4*)(g_T + c * 128 + off);
            a.x += t.x; a.y += t.y; a.z += t.z; a.w += t.w;
        }
        float4 b = *(const float4*)(bias + off);
        float4 r = make_float4(fmaf(a.x, ni, b.x), fmaf(a.y, ni, b.y),
                               fmaf(a.z, ni, b.z), fmaf(a.w, ni, b.w));
        if (RELU) {
            r.x = fmaxf(r.x, 0.f); r.y = fmaxf(r.y, 0.f);
            r.z = fmaxf(r.z, 0.f); r.w = fmaxf(r.w, 0.f);
        }
        float* dstp = (OUTSEL == 0) ? g_H1 : (OUTSEL == 1) ? g_H2 : Oext;
        *(float4*)(dstp + w * 128 + off) = r;
    } else {
        const int off = lane * 2;
        float2 a = make_float2(0.f, 0.f);
        int e = s0;
        for (; e + 4 <= s1; e += 4) {
            int c0 = g_col[e + 0], c1 = g_col[e + 1];
            int c2 = g_col[e + 2], c3 = g_col[e + 3];
            float2 t0 = *(const float2*)(g_T + c0 * 64 + off);
            float2 t1 = *(const float2*)(g_T + c1 * 64 + off);
            float2 t2 = *(const float2*)(g_T + c2 * 64 + off);
            float2 t3 = *(const float2*)(g_T + c3 * 64 + off);
            a.x += t0.x + t1.x + t2.x + t3.x;
            a.y += t0.y + t1.y + t2.y + t3.y;
        }
        for (; e < s1; ++e) {
            int c = g_col[e];
            float2 t = *(const float2*)(g_T + c * 64 + off);
            a.x += t.x; a.y += t.y;
        }
        float2 b = *(const float2*)(bias + off);
        float2 r = make_float2(fmaf(a.x, ni, b.x), fmaf(a.y, ni, b.y));
        if (RELU) { r.x = fmaxf(r.x, 0.f); r.y = fmaxf(r.y, 0.f); }
        float* dstp = (OUTSEL == 0) ? g_H1 : (OUTSEL == 1) ? g_H2 : Oext;
        *(float2*)(dstp + w * 64 + off) = r;
    }
}

// ---------------- driver ----------------
extern "C" void kernel_launch(void* const* d_in, const int* in_sizes, int n_in,
                              void* d_out, int out_size) {
    const float* x   = (const float*)d_in[0];
    const void*  src = d_in[1];
    const void*  dst = d_in[2];
    const float* W1 = (const float*)d_in[3];
    const float* b1 = (const float*)d_in[4];
    const float* W2 = (const float*)d_in[5];
    const float* b2 = (const float*)d_in[6];
    const float* W3 = (const float*)d_in[7];
    const float* b3 = (const float*)d_in[8];
    float* out = (float*)d_out;

    const int NB_N = (NN + 255) / 256;
    const int NB_E = (NE + 255) / 256;
    const int NB_G = (NN + 127) / 128;
    const int NB_A = (NN * 32 + 255) / 256;

    // graph preprocessing
    detect_kernel<<<1, 32>>>((const int*)src);
    init_kernel<<<NB_N, 256>>>();
    count_kernel<<<NB_E, 256>>>(src, dst);
    scanA_kernel<<<SCAN_BLK, 1024>>>();
    scanB_kernel<<<1, 32>>>();
    scanC_norm_kernel<<<NB_N, 256>>>();
    fill_kernel<<<NB_E, 256>>>(src, dst);

    // layer 1
    gemm_tc_kernel<128, 0><<<NB_G, 256>>>(x, W1);
    agg_kernel<128, true, 0><<<NB_A, 256>>>(b1, nullptr);

    // layer 2
    gemm_tc_kernel<128, 1><<<NB_G, 256>>>(nullptr, W2);
    agg_kernel<128, true, 1><<<NB_A, 256>>>(b2, nullptr);

    // layer 3
    gemm_tc_kernel<64, 2><<<NB_G, 256>>>(nullptr, W3);
    agg_kernel<64, false, 2><<<NB_A, 256>>>(b3, out);
}

// round 5
// speedup vs baseline: 1.1386x; 1.1386x over previous
#include <cuda_runtime.h>
#include <cuda_fp16.h>

#define NN 100000
#define NE 1600000
#define SCAN_BLK ((NN + 1023) / 1024)   // 98

// ---------------- scratch (static device allocations only) ----------------
__device__ __align__(16) __half g_T[NN * 128];   // fp16 gather payload
__device__ float g_H1[NN * 128];
__device__ float g_H2[NN * 128];
__device__ float g_norm_out[NN];
__device__ float g_norm_in[NN];
__device__ int   g_deg_out[NN];
__device__ int   g_deg_in[NN];
__device__ int   g_rowptr[NN + 1];
__device__ int   g_fill[NN];
__device__ int   g_col[NE];
__device__ int   g_bsum[SCAN_BLK];
__device__ int   g_is64;

// ---------------- index dtype detection ----------------
__global__ void detect_kernel(const int* __restrict__ src_raw) {
    if (threadIdx.x == 0 && blockIdx.x == 0) {
        int is64 = 1;
        for (int i = 0; i < 64; ++i)
            if (src_raw[2 * i + 1] != 0) { is64 = 0; break; }
        g_is64 = is64;
    }
}

__device__ __forceinline__ int load_idx(const void* p, int e, int is64) {
    if (is64) return (int)((const long long*)p)[e];
    return ((const int*)p)[e];
}

// ---------------- graph preprocessing ----------------
__global__ void init_kernel() {
    int i = blockIdx.x * blockDim.x + threadIdx.x;
    if (i < NN) { g_deg_out[i] = 0; g_deg_in[i] = 0; g_fill[i] = 0; }
}

__global__ void count_kernel(const void* __restrict__ src,
                             const void* __restrict__ dst) {
    int e = blockIdx.x * blockDim.x + threadIdx.x;
    int is64 = g_is64;
    if (e < NE) {
        atomicAdd(&g_deg_out[load_idx(src, e, is64)], 1);
        atomicAdd(&g_deg_in[load_idx(dst, e, is64)], 1);
    }
}

__global__ __launch_bounds__(1024) void scanA_kernel() {
    __shared__ int wsum[32];
    int i = blockIdx.x * 1024 + threadIdx.x;
    int lane = threadIdx.x & 31, wid = threadIdx.x >> 5;
    int v = (i < NN) ? g_deg_in[i] : 0;
    int x = v;
    #pragma unroll
    for (int o = 1; o < 32; o <<= 1) {
        int t = __shfl_up_sync(0xffffffffu, x, o);
        if (lane >= o) x += t;
    }
    if (lane == 31) wsum[wid] = x;
    __syncthreads();
    if (wid == 0) {
        int y = wsum[lane];
        #pragma unroll
        for (int o = 1; o < 32; o <<= 1) {
            int t = __shfl_up_sync(0xffffffffu, y, o);
            if (lane >= o) y += t;
        }
        wsum[lane] = y;
    }
    __syncthreads();
    int excl = x - v + (wid > 0 ? wsum[wid - 1] : 0);
    if (i < NN) g_rowptr[i] = excl;
    if (threadIdx.x == 1023) g_bsum[blockIdx.x] = excl + v;
}

__global__ void scanB_kernel() {
    if (threadIdx.x == 0) {
        int s = 0;
        for (int b = 0; b < SCAN_BLK; ++b) {
            int t = g_bsum[b];
            g_bsum[b] = s;
            s += t;
        }
        g_rowptr[NN] = s;
    }
}

__global__ void scanC_norm_kernel() {
    int i = blockIdx.x * blockDim.x + threadIdx.x;
    if (i < NN) {
        g_rowptr[i] += g_bsum[i >> 10];
        g_norm_out[i] = rsqrtf((float)max(g_deg_out[i], 1));
        g_norm_in[i]  = rsqrtf((float)max(g_deg_in[i], 1));
    }
}

__global__ void fill_kernel(const void* __restrict__ src,
                            const void* __restrict__ dst) {
    int e = blockIdx.x * blockDim.x + threadIdx.x;
    int is64 = g_is64;
    if (e < NE) {
        int d = load_idx(dst, e, is64);
        int p = g_rowptr[d] + atomicAdd(&g_fill[d], 1);
        g_col[p] = load_idx(src, e, is64);
    }
}

// ---------------- GEMM: g_T(half) = (A @ W) * norm_out[:,None] ----------------
// A [NN,128] row-major fp32, W [128,BN] row-major fp32.
// SRCSEL: 0 = Xext, 1 = g_H1, 2 = 0.9*g_H1 + 0.1*g_H2
template <int BN, int SRCSEL>
__global__ __launch_bounds__(256) void gemm_kernel(const float* __restrict__ Xext,
                                                   const float* __restrict__ W) {
    constexpr int BM = 128, BK = 16, TM = 8, TN = BN / 16;
    __shared__ float Xs[BK][BM];
    __shared__ float Ws[BK][BN];

    const int tid = threadIdx.x;
    const int tx = tid & 15;
    const int ty = tid >> 4;
    const int m0 = blockIdx.x * BM;

    float acc[TM][TN];
    #pragma unroll
    for (int i = 0; i < TM; ++i)
        #pragma unroll
        for (int j = 0; j < TN; ++j) acc[i][j] = 0.f;

    for (int kc = 0; kc < 128; kc += BK) {
        #pragma unroll
        for (int l = 0; l < (BM * BK) / 1024; ++l) {
            int lin = tid + l * 256;
            int row = lin >> 2;
            int kq  = (lin & 3) << 2;
            int gr  = m0 + row;
            float4 v = make_float4(0.f, 0.f, 0.f, 0.f);
            if (gr < NN) {
                if (SRCSEL == 0) {
                    v = *(const float4*)(Xext + gr * 128 + kc + kq);
                } else if (SRCSEL == 1) {
                    v = *(const float4*)(g_H1 + gr * 128 + kc + kq);
                } else {
                    float4 a = *(const float4*)(g_H1 + gr * 128 + kc + kq);
                    float4 b = *(const float4*)(g_H2 + gr * 128 + kc + kq);
                    v = make_float4(0.9f * a.x + 0.1f * b.x,
                                    0.9f * a.y + 0.1f * b.y,
                                    0.9f * a.z + 0.1f * b.z,
                                    0.9f * a.w + 0.1f * b.w);
                }
            }
            Xs[kq + 0][row] = v.x;
            Xs[kq + 1][row] = v.y;
            Xs[kq + 2][row] = v.z;
            Xs[kq + 3][row] = v.w;
        }
        #pragma unroll
        for (int l = 0; l < (BK * BN) / 1024; ++l) {
            int lin = tid + l * 256;
            int k = lin / (BN / 4);
            int nq = (lin % (BN / 4)) * 4;
            *(float4*)&Ws[k][nq] = *(const float4*)(W + (kc + k) * BN + nq);
        }
        __syncthreads();

        #pragma unroll
        for (int k = 0; k < BK; ++k) {
            float a[TM], b[TN];
            #pragma unroll
            for (int i = 0; i < TM; ++i) a[i] = Xs[k][ty * TM + i];
            #pragma unroll
            for (int j = 0; j < TN; ++j) b[j] = Ws[k][tx * TN + j];
            #pragma unroll
            for (int i = 0; i < TM; ++i)
                #pragma unroll
                for (int j = 0; j < TN; ++j) acc[i][j] += a[i] * b[j];
        }
        __syncthreads();
    }

    // epilogue: scale by norm_out, convert to fp16, store to g_T (stride BN)
    #pragma unroll
    for (int i = 0; i < TM; ++i) {
        int m = m0 + ty * TM + i;
        if (m < NN) {
            float no = g_norm_out[m];
            __half2 h[TN / 2];
            #pragma unroll
            for (int j = 0; j < TN; j += 2)
                h[j / 2] = __floats2half2_rn(acc[i][j] * no, acc[i][j + 1] * no);
            if (TN == 8) {
                *(uint4*)&g_T[m * BN + tx * TN] =
                    *reinterpret_cast<uint4*>(h);
            } else {
                *(uint2*)&g_T[m * BN + tx * TN] =
                    *reinterpret_cast<uint2*>(h);
            }
        }
    }
}

// ---------------- aggregation: out = (sum T[src]) * norm_in + b ----------------
// one warp per node; FEAT=128: 4 halves/lane (8B), FEAT=64: 2 halves/lane (4B)
template <int FEAT, bool RELU, int OUTSEL>   // OUTSEL: 0=g_H1, 1=g_H2, 2=Oext
__global__ __launch_bounds__(256) void agg_kernel(const float* __restrict__ bias,
                                                  float* __restrict__ Oext) {
    int w = (blockIdx.x * 256 + threadIdx.x) >> 5;
    int lane = threadIdx.x & 31;
    if (w >= NN) return;
    int s0 = g_rowptr[w];
    int s1 = g_rowptr[w + 1];
    float ni = g_norm_in[w];
    const __half* T = g_T;

    if (FEAT == 128) {
        const int off = lane * 4;
        float4 a = make_float4(0.f, 0.f, 0.f, 0.f);
        int e = s0;
        for (; e + 4 <= s1; e += 4) {
            int c0 = g_col[e + 0], c1 = g_col[e + 1];
            int c2 = g_col[e + 2], c3 = g_col[e + 3];
            uint2 u0 = *(const uint2*)(T + c0 * 128 + off);
            uint2 u1 = *(const uint2*)(T + c1 * 128 + off);
            uint2 u2 = *(const uint2*)(T + c2 * 128 + off);
            uint2 u3 = *(const uint2*)(T + c3 * 128 + off);
            float2 p, q;
            p = __half22float2(*(__half2*)&u0.x); q = __half22float2(*(__half2*)&u0.y);
            a.x += p.x; a.y += p.y; a.z += q.x; a.w += q.y;
            p = __half22float2(*(__half2*)&u1.x); q = __half22float2(*(__half2*)&u1.y);
            a.x += p.x; a.y += p.y; a.z += q.x; a.w += q.y;
            p = __half22float2(*(__half2*)&u2.x); q = __half22float2(*(__half2*)&u2.y);
            a.x += p.x; a.y += p.y; a.z += q.x; a.w += q.y;
            p = __half22float2(*(__half2*)&u3.x); q = __half22float2(*(__half2*)&u3.y);
            a.x += p.x; a.y += p.y; a.z += q.x; a.w += q.y;
        }
        for (; e < s1; ++e) {
            int c = g_col[e];
            uint2 u = *(const uint2*)(T + c * 128 + off);
            float2 p = __half22float2(*(__half2*)&u.x);
            float2 q = __half22float2(*(__half2*)&u.y);
            a.x += p.x; a.y += p.y; a.z += q.x; a.w += q.y;
        }
        float4 b = *(const float4*)(bias + off);
        float4 r = make_float4(fmaf(a.x, ni, b.x), fmaf(a.y, ni, b.y),
                               fmaf(a.z, ni, b.z), fmaf(a.w, ni, b.w));
        if (RELU) {
            r.x = fmaxf(r.x, 0.f); r.y = fmaxf(r.y, 0.f);
            r.z = fmaxf(r.z, 0.f); r.w = fmaxf(r.w, 0.f);
        }
        float* dstp = (OUTSEL == 0) ? g_H1 : (OUTSEL == 1) ? g_H2 : Oext;
        *(float4*)(dstp + w * 128 + off) = r;
    } else {
        const int off = lane * 2;
        float2 a = make_float2(0.f, 0.f);
        int e = s0;
        for (; e + 4 <= s1; e += 4) {
            int c0 = g_col[e + 0], c1 = g_col[e + 1];
            int c2 = g_col[e + 2], c3 = g_col[e + 3];
            unsigned u0 = *(const unsigned*)(T + c0 * 64 + off);
            unsigned u1 = *(const unsigned*)(T + c1 * 64 + off);
            unsigned u2 = *(const unsigned*)(T + c2 * 64 + off);
            unsigned u3 = *(const unsigned*)(T + c3 * 64 + off);
            float2 p;
            p = __half22float2(*(__half2*)&u0); a.x += p.x; a.y += p.y;
            p = __half22float2(*(__half2*)&u1); a.x += p.x; a.y += p.y;
            p = __half22float2(*(__half2*)&u2); a.x += p.x; a.y += p.y;
            p = __half22float2(*(__half2*)&u3); a.x += p.x; a.y += p.y;
        }
        for (; e < s1; ++e) {
            int c = g_col[e];
            unsigned u = *(const unsigned*)(T + c * 64 + off);
            float2 p = __half22float2(*(__half2*)&u);
            a.x += p.x; a.y += p.y;
        }
        float2 b = *(const float2*)(bias + off);
        float2 r = make_float2(fmaf(a.x, ni, b.x), fmaf(a.y, ni, b.y));
        if (RELU) { r.x = fmaxf(r.x, 0.f); r.y = fmaxf(r.y, 0.f); }
        float* dstp = (OUTSEL == 0) ? g_H1 : (OUTSEL == 1) ? g_H2 : Oext;
        *(float2*)(dstp + w * 64 + off) = r;
    }
}

// ---------------- driver ----------------
extern "C" void kernel_launch(void* const* d_in, const int* in_sizes, int n_in,
                              void* d_out, int out_size) {
    const float* x   = (const float*)d_in[0];
    const void*  src = d_in[1];
    const void*  dst = d_in[2];
    const float* W1 = (const float*)d_in[3];
    const float* b1 = (const float*)d_in[4];
    const float* W2 = (const float*)d_in[5];
    const float* b2 = (const float*)d_in[6];
    const float* W3 = (const float*)d_in[7];
    const float* b3 = (const float*)d_in[8];
    float* out = (float*)d_out;

    const int NB_N = (NN + 255) / 256;
    const int NB_E = (NE + 255) / 256;
    const int NB_G = (NN + 127) / 128;
    const int NB_A = (NN * 32 + 255) / 256;

    // graph preprocessing
    detect_kernel<<<1, 32>>>((const int*)src);
    init_kernel<<<NB_N, 256>>>();
    count_kernel<<<NB_E, 256>>>(src, dst);
    scanA_kernel<<<SCAN_BLK, 1024>>>();
    scanB_kernel<<<1, 32>>>();
    scanC_norm_kernel<<<NB_N, 256>>>();
    fill_kernel<<<NB_E, 256>>>(src, dst);

    // layer 1
    gemm_kernel<128, 0><<<NB_G, 256>>>(x, W1);
    agg_kernel<128, true, 0><<<NB_A, 256>>>(b1, nullptr);

    // layer 2
    gemm_kernel<128, 1><<<NB_G, 256>>>(nullptr, W2);
    agg_kernel<128, true, 1><<<NB_A, 256>>>(b2, nullptr);

    // layer 3
    gemm_kernel<64, 2><<<NB_G, 256>>>(nullptr, W3);
    agg_kernel<64, false, 2><<<NB_A, 256>>>(b3, out);
}